// round 3
// baseline (speedup 1.0000x reference)
#include <cuda_runtime.h>
#include <math.h>

#define Bsz 8
#define Dd 512
#define Hh 8
#define Ee 64
#define DI 1024
#define Ss 64
#define Rr 32
#define DFF 2048
#define LL 1152
#define Mrows (Bsz*LL)   /* 9216 */

// ---------------- scratch (static __device__, no allocation) ----------------
__device__ float g_q[Mrows*Dd];
__device__ float g_k[Mrows*Dd];
__device__ float g_v[Mrows*Dd];
__device__ float g_attnO[Mrows*Dd];
__device__ float g_attn_out[Mrows*Dd];
__device__ float g_xz[Mrows*2*DI];
__device__ float g_uact[Mrows*DI];
__device__ float g_xdbc[Mrows*160];
__device__ float g_delta[Mrows*DI];
__device__ float g_y[Mrows*DI];
__device__ float g_mamba[Mrows*Dd];
__device__ float g_h[Mrows*Dd];
__device__ float g_hn[Mrows*Dd];
__device__ float g_mid[Mrows*DFF];

// ---------------- generic SGEMM: C = A(MxK, lda) @ W(NxK)^T (+bias, +epi) ----
enum { EPI_NONE = 0, EPI_SOFTPLUS = 1, EPI_GELU = 2, EPI_ADD = 3 };

template<int EPI>
__global__ __launch_bounds__(256) void sgemm_k(
    const float* __restrict__ A, int lda,
    const float* __restrict__ W,
    const float* __restrict__ bias,
    const float* __restrict__ add,
    float* __restrict__ C, int M, int N, int K)
{
    __shared__ float As[8][128];
    __shared__ float Ws[8][64];
    int tid = threadIdx.x;
    int tx = tid & 15, ty = tid >> 4;
    int m0 = blockIdx.y * 128, n0 = blockIdx.x * 64;

    float acc[8][4];
#pragma unroll
    for (int i = 0; i < 8; i++)
#pragma unroll
        for (int j = 0; j < 4; j++) acc[i][j] = 0.f;

    int arow = tid >> 1;
    int akq  = (tid & 1) * 4;
    const float* Aptr = A + (size_t)(m0 + arow) * lda + akq;
    int wrow = (tid & 127) >> 1;
    int wkq  = (tid & 1) * 4;
    bool wvalid = (tid < 128) && (n0 + wrow < N);
    const float* Wptr = W + (size_t)(n0 + wrow) * K + wkq;

    for (int k0 = 0; k0 < K; k0 += 8) {
        float4 av = *(const float4*)(Aptr + k0);
        As[akq+0][arow] = av.x; As[akq+1][arow] = av.y;
        As[akq+2][arow] = av.z; As[akq+3][arow] = av.w;
        if (tid < 128) {
            float4 wv = make_float4(0.f, 0.f, 0.f, 0.f);
            if (wvalid) wv = *(const float4*)(Wptr + k0);
            Ws[wkq+0][wrow] = wv.x; Ws[wkq+1][wrow] = wv.y;
            Ws[wkq+2][wrow] = wv.z; Ws[wkq+3][wrow] = wv.w;
        }
        __syncthreads();
#pragma unroll
        for (int kk = 0; kk < 8; kk++) {
            float4 a0 = *(const float4*)&As[kk][ty*8];
            float4 a1 = *(const float4*)&As[kk][ty*8+4];
            float4 b0 = *(const float4*)&Ws[kk][tx*4];
            float ar[8] = {a0.x,a0.y,a0.z,a0.w,a1.x,a1.y,a1.z,a1.w};
            float br[4] = {b0.x,b0.y,b0.z,b0.w};
#pragma unroll
            for (int i = 0; i < 8; i++)
#pragma unroll
                for (int j = 0; j < 4; j++)
                    acc[i][j] = fmaf(ar[i], br[j], acc[i][j]);
        }
        __syncthreads();
    }

#pragma unroll
    for (int i = 0; i < 8; i++) {
        int m = m0 + ty*8 + i;
#pragma unroll
        for (int j = 0; j < 4; j++) {
            int n = n0 + tx*4 + j;
            if (n < N) {
                float vv = acc[i][j];
                if (bias) vv += bias[n];
                if (EPI == EPI_SOFTPLUS) {
                    vv = (vv > 20.f) ? vv : log1pf(expf(vv));
                } else if (EPI == EPI_GELU) {
                    vv = 0.5f * vv * (1.f + erff(vv * 0.7071067811865475f));
                } else if (EPI == EPI_ADD) {
                    vv += add[(size_t)m * N + n];
                }
                C[(size_t)m * N + n] = vv;
            }
        }
    }
}

// ---------------- flash attention: 64-row Q tile, 32-key tiles ---------------
__global__ __launch_bounds__(256) void attn_k(
    const float* __restrict__ q, const float* __restrict__ k,
    const float* __restrict__ v, const unsigned char* __restrict__ mask,
    float* __restrict__ o)
{
    __shared__ float QsT[64][64];   // [e][m]
    __shared__ float KsT[64][32];   // [e][n]
    __shared__ float Vs [32][64];   // [n][e]
    __shared__ float PsT[32][68];   // [n][m] (padded)

    int qt = blockIdx.x, h = blockIdx.y, b = blockIdx.z;
    int tid = threadIdx.x;
    int tx = tid & 15, ty = tid >> 4;
    const size_t bL = (size_t)b * LL;
    int q0 = qt * 64;

    for (int i = tid; i < 1024; i += 256) {
        int m = i >> 4, e4 = (i & 15) * 4;
        float4 qv = *(const float4*)&q[(bL + q0 + m) * Dd + h*Ee + e4];
        QsT[e4+0][m] = qv.x; QsT[e4+1][m] = qv.y;
        QsT[e4+2][m] = qv.z; QsT[e4+3][m] = qv.w;
    }

    float acc[4][4];
#pragma unroll
    for (int i = 0; i < 4; i++)
#pragma unroll
        for (int j = 0; j < 4; j++) acc[i][j] = 0.f;
    float mrow[4] = {-INFINITY, -INFINITY, -INFINITY, -INFINITY};
    float lrow[4] = {0.f, 0.f, 0.f, 0.f};
    const float scale = 0.125f;   // 1/sqrt(64)

    for (int n0k = 0; n0k < LL; n0k += 32) {
        __syncthreads();
        for (int i = tid; i < 512; i += 256) {
            int n = i >> 4, e4 = (i & 15) * 4;
            size_t gr = (bL + n0k + n) * Dd + h*Ee + e4;
            float4 kv = *(const float4*)&k[gr];
            KsT[e4+0][n] = kv.x; KsT[e4+1][n] = kv.y;
            KsT[e4+2][n] = kv.z; KsT[e4+3][n] = kv.w;
            float4 vv = *(const float4*)&v[gr];
            *(float4*)&Vs[n][e4] = vv;
        }
        __syncthreads();

        float s[4][2];
#pragma unroll
        for (int i = 0; i < 4; i++) { s[i][0] = 0.f; s[i][1] = 0.f; }
#pragma unroll 16
        for (int e = 0; e < 64; e++) {
            float4 qv = *(const float4*)&QsT[e][ty*4];
            float2 kv = *(const float2*)&KsT[e][tx*2];
            s[0][0] = fmaf(qv.x, kv.x, s[0][0]); s[0][1] = fmaf(qv.x, kv.y, s[0][1]);
            s[1][0] = fmaf(qv.y, kv.x, s[1][0]); s[1][1] = fmaf(qv.y, kv.y, s[1][1]);
            s[2][0] = fmaf(qv.z, kv.x, s[2][0]); s[2][1] = fmaf(qv.z, kv.y, s[2][1]);
            s[3][0] = fmaf(qv.w, kv.x, s[3][0]); s[3][1] = fmaf(qv.w, kv.y, s[3][1]);
        }

        unsigned char mk0 = mask[bL + n0k + tx*2 + 0];
        unsigned char mk1 = mask[bL + n0k + tx*2 + 1];
        float p[4][2];
#pragma unroll
        for (int i = 0; i < 4; i++) {
            float s0 = s[i][0] * scale, s1 = s[i][1] * scale;
            if (mk0) s0 = -INFINITY;
            if (mk1) s1 = -INFINITY;
            float t = fmaxf(s0, s1);
#pragma unroll
            for (int off = 1; off < 16; off <<= 1)
                t = fmaxf(t, __shfl_xor_sync(0xffffffffu, t, off));
            float mnew = fmaxf(mrow[i], t);
            float p0 = __expf(s0 - mnew), p1 = __expf(s1 - mnew);
            float rs = p0 + p1;
#pragma unroll
            for (int off = 1; off < 16; off <<= 1)
                rs += __shfl_xor_sync(0xffffffffu, rs, off);
            float corr = __expf(mrow[i] - mnew);
            lrow[i] = lrow[i] * corr + rs;
            mrow[i] = mnew;
            acc[i][0] *= corr; acc[i][1] *= corr;
            acc[i][2] *= corr; acc[i][3] *= corr;
            p[i][0] = p0; p[i][1] = p1;
        }
#pragma unroll
        for (int j = 0; j < 2; j++) {
            int n = tx*2 + j;
            *(float4*)&PsT[n][ty*4] = make_float4(p[0][j], p[1][j], p[2][j], p[3][j]);
        }
        __syncthreads();
#pragma unroll 8
        for (int n = 0; n < 32; n++) {
            float4 pv = *(const float4*)&PsT[n][ty*4];
            float4 vv = *(const float4*)&Vs[n][tx*4];
            acc[0][0] = fmaf(pv.x, vv.x, acc[0][0]); acc[0][1] = fmaf(pv.x, vv.y, acc[0][1]);
            acc[0][2] = fmaf(pv.x, vv.z, acc[0][2]); acc[0][3] = fmaf(pv.x, vv.w, acc[0][3]);
            acc[1][0] = fmaf(pv.y, vv.x, acc[1][0]); acc[1][1] = fmaf(pv.y, vv.y, acc[1][1]);
            acc[1][2] = fmaf(pv.y, vv.z, acc[1][2]); acc[1][3] = fmaf(pv.y, vv.w, acc[1][3]);
            acc[2][0] = fmaf(pv.z, vv.x, acc[2][0]); acc[2][1] = fmaf(pv.z, vv.y, acc[2][1]);
            acc[2][2] = fmaf(pv.z, vv.z, acc[2][2]); acc[2][3] = fmaf(pv.z, vv.w, acc[2][3]);
            acc[3][0] = fmaf(pv.w, vv.x, acc[3][0]); acc[3][1] = fmaf(pv.w, vv.y, acc[3][1]);
            acc[3][2] = fmaf(pv.w, vv.z, acc[3][2]); acc[3][3] = fmaf(pv.w, vv.w, acc[3][3]);
        }
    }

#pragma unroll
    for (int i = 0; i < 4; i++) {
        float inv = 1.f / lrow[i];
        size_t row = (bL + q0 + ty*4 + i) * Dd + h*Ee + tx*4;
        *(float4*)&o[row] = make_float4(acc[i][0]*inv, acc[i][1]*inv,
                                        acc[i][2]*inv, acc[i][3]*inv);
    }
}

// ---------------- causal depthwise conv (KC=4) + SiLU ------------------------
__global__ void conv_silu_k(const float* __restrict__ xz,
                            const float* __restrict__ cw,
                            const float* __restrict__ cb,
                            float* __restrict__ uact)
{
    int idx = blockIdx.x * 256 + threadIdx.x;     // over Mrows*DI
    int r = idx >> 10;
    int j = idx & 1023;
    int t = r % LL;
    float acc = cb[j];
#pragma unroll
    for (int kk = 0; kk < 4; kk++) {
        int tt = t + kk - 3;
        if (tt >= 0)
            acc = fmaf(xz[(size_t)(r + kk - 3) * (2*DI) + j], cw[j*4 + kk], acc);
    }
    uact[idx] = acc / (1.f + expf(-acc));
}

// ---------------- selective scan: 1 warp per (b,d), 2 states/lane ------------
__global__ __launch_bounds__(512) void scan_k(
    const float* __restrict__ delta, const float* __restrict__ uact,
    const float* __restrict__ xdbc, const float* __restrict__ A_log,
    float* __restrict__ y)
{
    __shared__ float sB[16][64];
    __shared__ float sC[16][64];
    __shared__ float sdt[16][16];
    __shared__ float su[16][16];

    int b = blockIdx.y;
    int d0 = blockIdx.x * 16;
    int tid = threadIdx.x;
    int w = tid >> 5, l = tid & 31;
    int d = d0 + w;
    float a0 = -expf(A_log[d*Ss + l]);
    float a1 = -expf(A_log[d*Ss + l + 32]);
    float h0 = 0.f, h1 = 0.f;
    size_t base = (size_t)b * LL;

    for (int t0 = 0; t0 < LL; t0 += 16) {
        __syncthreads();
        for (int i = tid; i < 2048; i += 512) {
            int tt = i >> 7, c = i & 127;
            float val = xdbc[(base + t0 + tt) * 160 + 32 + c];
            if (c < 64) sB[tt][c] = val; else sC[tt][c - 64] = val;
        }
        if (tid < 256) {
            sdt[tid >> 4][tid & 15] = delta[(base + t0 + (tid >> 4)) * DI + d0 + (tid & 15)];
        } else {
            int jj = tid - 256;
            su[jj >> 4][jj & 15] = uact[(base + t0 + (jj >> 4)) * DI + d0 + (jj & 15)];
        }
        __syncthreads();
#pragma unroll 4
        for (int tt = 0; tt < 16; tt++) {
            float dt  = sdt[tt][w];
            float dtu = dt * su[tt][w];
            float dA0 = __expf(dt * a0);
            float dA1 = __expf(dt * a1);
            h0 = fmaf(h0, dA0, dtu * sB[tt][l]);
            h1 = fmaf(h1, dA1, dtu * sB[tt][l + 32]);
            float yv = h0 * sC[tt][l] + h1 * sC[tt][l + 32];
#pragma unroll
            for (int off = 16; off > 0; off >>= 1)
                yv += __shfl_xor_sync(0xffffffffu, yv, off);
            if (l == 0) y[(base + t0 + tt) * DI + d] = yv;
        }
    }
}

// ---------------- gate: y = (y + uact*D) * silu(z) ---------------------------
__global__ void gate_k(float* __restrict__ y, const float* __restrict__ uact,
                       const float* __restrict__ xz, const float* __restrict__ Dssm)
{
    int idx = blockIdx.x * 256 + threadIdx.x;   // over Mrows*DI
    int r = idx >> 10, j = idx & 1023;
    float z  = xz[(size_t)r * (2*DI) + DI + j];
    float yv = y[idx] + uact[idx] * Dssm[j];
    y[idx] = yv * (z / (1.f + expf(-z)));
}

// ---------------- fused residual-sum + LN1 + LN2 -----------------------------
__device__ __forceinline__ float blockSum128(float v, float* sm)
{
#pragma unroll
    for (int off = 16; off > 0; off >>= 1)
        v += __shfl_xor_sync(0xffffffffu, v, off);
    if ((threadIdx.x & 31) == 0) sm[threadIdx.x >> 5] = v;
    __syncthreads();
    float r = sm[0] + sm[1] + sm[2] + sm[3];
    __syncthreads();
    return r;
}

__global__ __launch_bounds__(128) void combine_ln_k(
    const float* __restrict__ xf, const float* __restrict__ attn,
    const float* __restrict__ mamba,
    const float* __restrict__ g1, const float* __restrict__ b1,
    const float* __restrict__ g2, const float* __restrict__ b2,
    float* __restrict__ h, float* __restrict__ hn)
{
    __shared__ float sm[4];
    int r = blockIdx.x, tid = threadIdx.x;
    size_t base = (size_t)r * Dd;
    float vv[4];
#pragma unroll
    for (int i = 0; i < 4; i++) {
        int c = tid + i*128;
        vv[i] = xf[base+c] + attn[base+c] + mamba[base+c];
    }
    float s = vv[0] + vv[1] + vv[2] + vv[3];
    float mean = blockSum128(s, sm) * (1.f/512.f);
    float sq = 0.f;
#pragma unroll
    for (int i = 0; i < 4; i++) { float dd = vv[i] - mean; sq = fmaf(dd, dd, sq); }
    float var = blockSum128(sq, sm) * (1.f/512.f);
    float inv = rsqrtf(var + 1e-5f);
    float hv[4];
#pragma unroll
    for (int i = 0; i < 4; i++) {
        int c = tid + i*128;
        hv[i] = (vv[i] - mean) * inv * g1[c] + b1[c];
        h[base+c] = hv[i];
    }
    float s2 = hv[0] + hv[1] + hv[2] + hv[3];
    float mean2 = blockSum128(s2, sm) * (1.f/512.f);
    float sq2 = 0.f;
#pragma unroll
    for (int i = 0; i < 4; i++) { float dd = hv[i] - mean2; sq2 = fmaf(dd, dd, sq2); }
    float var2 = blockSum128(sq2, sm) * (1.f/512.f);
    float inv2 = rsqrtf(var2 + 1e-6f);
#pragma unroll
    for (int i = 0; i < 4; i++) {
        int c = tid + i*128;
        hn[base+c] = (hv[i] - mean2) * inv2 * g2[c] + b2[c];
    }
}

// ---------------- launch -----------------------------------------------------
extern "C" void kernel_launch(void* const* d_in, const int* in_sizes, int n_in,
                              void* d_out, int out_size)
{
    const float* x          = (const float*)d_in[0];
    const unsigned char* mask = (const unsigned char*)d_in[1];
    const float* Wq = (const float*)d_in[2];   const float* bq = (const float*)d_in[3];
    const float* Wk = (const float*)d_in[4];   const float* bk = (const float*)d_in[5];
    const float* Wv = (const float*)d_in[6];   const float* bv = (const float*)d_in[7];
    const float* Wo = (const float*)d_in[8];   const float* bo = (const float*)d_in[9];
    const float* in_proj_w = (const float*)d_in[10];
    const float* conv_w    = (const float*)d_in[11];
    const float* conv_b    = (const float*)d_in[12];
    const float* x_proj_w  = (const float*)d_in[13];
    const float* dt_proj_w = (const float*)d_in[14];
    const float* dt_proj_b = (const float*)d_in[15];
    const float* A_log     = (const float*)d_in[16];
    const float* D_ssm     = (const float*)d_in[17];
    const float* out_proj_w= (const float*)d_in[18];
    const float* ln1_g = (const float*)d_in[19]; const float* ln1_b = (const float*)d_in[20];
    const float* ffn_w1= (const float*)d_in[21]; const float* ffn_b1= (const float*)d_in[22];
    const float* ffn_w2= (const float*)d_in[23]; const float* ffn_b2= (const float*)d_in[24];
    const float* ln2_g = (const float*)d_in[25]; const float* ln2_b = (const float*)d_in[26];
    float* out = (float*)d_out;

    float *q,*k,*v,*attnO,*attn_out,*xz,*uact,*xdbc,*delta,*y,*mamba,*h,*hn,*mid;
    cudaGetSymbolAddress((void**)&q,        g_q);
    cudaGetSymbolAddress((void**)&k,        g_k);
    cudaGetSymbolAddress((void**)&v,        g_v);
    cudaGetSymbolAddress((void**)&attnO,    g_attnO);
    cudaGetSymbolAddress((void**)&attn_out, g_attn_out);
    cudaGetSymbolAddress((void**)&xz,       g_xz);
    cudaGetSymbolAddress((void**)&uact,     g_uact);
    cudaGetSymbolAddress((void**)&xdbc,     g_xdbc);
    cudaGetSymbolAddress((void**)&delta,    g_delta);
    cudaGetSymbolAddress((void**)&y,        g_y);
    cudaGetSymbolAddress((void**)&mamba,    g_mamba);
    cudaGetSymbolAddress((void**)&h,        g_h);
    cudaGetSymbolAddress((void**)&hn,       g_hn);
    cudaGetSymbolAddress((void**)&mid,      g_mid);

    const int MY = Mrows / 128;   // 72

    // attention branch
    sgemm_k<EPI_NONE><<<dim3(Dd/64,   MY), 256>>>(x, Dd, Wq, bq, nullptr, q, Mrows, Dd, Dd);
    sgemm_k<EPI_NONE><<<dim3(Dd/64,   MY), 256>>>(x, Dd, Wk, bk, nullptr, k, Mrows, Dd, Dd);
    sgemm_k<EPI_NONE><<<dim3(Dd/64,   MY), 256>>>(x, Dd, Wv, bv, nullptr, v, Mrows, Dd, Dd);
    attn_k<<<dim3(LL/64, Hh, Bsz), 256>>>(q, k, v, mask, attnO);
    sgemm_k<EPI_NONE><<<dim3(Dd/64,   MY), 256>>>(attnO, Dd, Wo, bo, nullptr, attn_out, Mrows, Dd, Dd);

    // mamba branch
    sgemm_k<EPI_NONE><<<dim3(2*DI/64, MY), 256>>>(x, Dd, in_proj_w, nullptr, nullptr, xz, Mrows, 2*DI, Dd);
    conv_silu_k<<<Mrows*DI/256, 256>>>(xz, conv_w, conv_b, uact);
    sgemm_k<EPI_NONE><<<dim3(3,       MY), 256>>>(uact, DI, x_proj_w, nullptr, nullptr, xdbc, Mrows, 160, DI);
    sgemm_k<EPI_SOFTPLUS><<<dim3(DI/64, MY), 256>>>(xdbc, 160, dt_proj_w, dt_proj_b, nullptr, delta, Mrows, DI, Rr);
    scan_k<<<dim3(DI/16, Bsz), 512>>>(delta, uact, xdbc, A_log, y);
    gate_k<<<Mrows*DI/256, 256>>>(y, uact, xz, D_ssm);
    sgemm_k<EPI_NONE><<<dim3(Dd/64,   MY), 256>>>(y, DI, out_proj_w, nullptr, nullptr, mamba, Mrows, Dd, DI);

    // combine + double layernorm
    combine_ln_k<<<Mrows, 128>>>(x, attn_out, mamba, ln1_g, ln1_b, ln2_g, ln2_b, h, hn);

    // FFN
    sgemm_k<EPI_GELU><<<dim3(DFF/64, MY), 256>>>(hn, Dd, ffn_w1, ffn_b1, nullptr, mid, Mrows, DFF, Dd);
    sgemm_k<EPI_ADD><<<dim3(Dd/64,   MY), 256>>>(mid, DFF, ffn_w2, ffn_b2, h, out, Mrows, Dd, DFF);
}